// round 1
// baseline (speedup 1.0000x reference)
#include <cuda_runtime.h>
#include <math.h>

#define B 4
#define S 512
#define E 512
#define H 8
#define DH 64
#define HID 128
#define M (B*S)      // 2048
#define BH (B*H)     // 32

// ---------------- scratch (device globals; no allocation allowed) ----------
__device__ float  g_q[BH*S*DH];        // [b,h,s,d] (pre-scaled by DH^-0.5)
__device__ float  g_k[BH*S*DH];
__device__ float  g_v[BH*S*DH];
__device__ float  g_scores[(size_t)BH*S*S];  // raw scores [b,h,i,j]
__device__ float  g_ma[(size_t)B*S*S];       // head-mean of clipped scores
__device__ float  g_t0[(size_t)B*S*S];       // sig * Fm (pre batch-affine)
__device__ float  g_ao[M*E];                 // attention output [b,s,h,d]
__device__ float  g_rowmax[BH*S];
__device__ float  g_rowsum[BH*S];
__device__ double g_sums[B*4];               // per-batch: sum t0, t0^2, ma, ma^2
__device__ float  g_AC[B*2];                 // per-batch affine A_b, C_b

// ---------------- helpers --------------------------------------------------
__device__ __forceinline__ float clampf(float x, float lo, float hi) {
    return fminf(fmaxf(x, lo), hi);
}
// nan_to_num(nan=0, posinf=10, neginf=-10) then clip(-15,15)
__device__ __forceinline__ float nnclip15(float x) {
    if (isnan(x)) x = 0.f;
    else if (isinf(x)) x = (x > 0.f) ? 10.f : -10.f;
    return clampf(x, -15.f, 15.f);
}

__device__ __forceinline__ float blockSum(float v, float* red) {
    int tid = threadIdx.x;
    __syncthreads();
    red[tid] = v;
    __syncthreads();
    #pragma unroll
    for (int s = 128; s > 0; s >>= 1) {
        if (tid < s) red[tid] += red[tid + s];
        __syncthreads();
    }
    return red[0];
}
__device__ __forceinline__ float blockMax(float v, float* red) {
    int tid = threadIdx.x;
    __syncthreads();
    red[tid] = v;
    __syncthreads();
    #pragma unroll
    for (int s = 128; s > 0; s >>= 1) {
        if (tid < s) red[tid] = fmaxf(red[tid], red[tid + s]);
        __syncthreads();
    }
    return red[0];
}

// ---------------- kernel 0: zero accumulators ------------------------------
__global__ void zero_kernel() {
    int t = threadIdx.x;
    if (t < B*4) g_sums[t] = 0.0;
}

// ---------------- kernel 1: QKV projection (A @ W^T + b) -------------------
// grid: (E/64 = H, M/64, 3), block 256. Writes [b,h,s,d] layout.
__global__ void qkv_kernel(const float* __restrict__ x,
                           const float* __restrict__ wq, const float* __restrict__ bq,
                           const float* __restrict__ wk, const float* __restrict__ bk,
                           const float* __restrict__ wv, const float* __restrict__ bv)
{
    __shared__ __align__(16) float As[64][68];   // [k][m]
    __shared__ __align__(16) float Ws[64][68];   // [k][o]
    int which = blockIdx.z;
    const float* Wp = (which == 0) ? wq : (which == 1) ? wk : wv;
    const float* bp = (which == 0) ? bq : (which == 1) ? bk : bv;
    float* outp     = (which == 0) ? g_q : (which == 1) ? g_k : g_v;
    float scale = (which == 0) ? 0.125f : 1.0f;  // DH^-0.5

    int h  = blockIdx.x;
    int n0 = h * 64;
    int m0 = blockIdx.y * 64;
    int tid = threadIdx.x;
    int tx = tid & 15, ty = tid >> 4;
    float c[4][4] = {};

    for (int kt = 0; kt < 8; ++kt) {
        int k0 = kt * 64;
        #pragma unroll
        for (int l = 0; l < 16; ++l) {
            int idx = tid + l * 256;
            int r = idx >> 6, cc = idx & 63;
            As[cc][r] = x [(m0 + r) * E + k0 + cc];
            Ws[cc][r] = Wp[(n0 + r) * E + k0 + cc];
        }
        __syncthreads();
        #pragma unroll
        for (int kk = 0; kk < 64; ++kk) {
            float4 av = *(const float4*)&As[kk][ty * 4];
            float4 bw = *(const float4*)&Ws[kk][tx * 4];
            float a[4] = {av.x, av.y, av.z, av.w};
            float bb[4] = {bw.x, bw.y, bw.z, bw.w};
            #pragma unroll
            for (int i = 0; i < 4; i++)
                #pragma unroll
                for (int j = 0; j < 4; j++)
                    c[i][j] += a[i] * bb[j];
        }
        __syncthreads();
    }
    #pragma unroll
    for (int i = 0; i < 4; i++) {
        int m = m0 + ty * 4 + i;
        int b = m >> 9, s = m & 511;
        float* dst = outp + (((size_t)(b * H + h) * S + s) * DH) + tx * 4;
        #pragma unroll
        for (int j = 0; j < 4; j++) {
            int o = n0 + tx * 4 + j;
            dst[j] = (c[i][j] + bp[o]) * scale;
        }
    }
}

// ---------------- kernel 2: scores = q @ k^T per (b,h) ---------------------
// grid: (S/64, S/64, BH), block 256
__global__ void scores_kernel() {
    __shared__ __align__(16) float Qs[64][68];   // [d][i]
    __shared__ __align__(16) float Ks[64][68];   // [d][j]
    int bh = blockIdx.z;
    int i0 = blockIdx.y * 64, j0 = blockIdx.x * 64;
    int tid = threadIdx.x, tx = tid & 15, ty = tid >> 4;
    const float* qb = g_q + (size_t)bh * S * DH;
    const float* kb = g_k + (size_t)bh * S * DH;
    #pragma unroll
    for (int l = 0; l < 16; ++l) {
        int idx = tid + l * 256;
        int r = idx >> 6, d = idx & 63;
        Qs[d][r] = qb[(i0 + r) * DH + d];
        Ks[d][r] = kb[(j0 + r) * DH + d];
    }
    __syncthreads();
    float c[4][4] = {};
    #pragma unroll
    for (int kk = 0; kk < 64; ++kk) {
        float4 av = *(const float4*)&Qs[kk][ty * 4];
        float4 bw = *(const float4*)&Ks[kk][tx * 4];
        float a[4] = {av.x, av.y, av.z, av.w};
        float bb[4] = {bw.x, bw.y, bw.z, bw.w};
        #pragma unroll
        for (int i = 0; i < 4; i++)
            #pragma unroll
            for (int j = 0; j < 4; j++)
                c[i][j] += a[i] * bb[j];
    }
    float* dst = g_scores + ((size_t)bh * S + i0) * S + j0;
    #pragma unroll
    for (int i = 0; i < 4; i++)
        #pragma unroll
        for (int j = 0; j < 4; j++)
            dst[(size_t)(ty * 4 + i) * S + tx * 4 + j] = c[i][j];
}

// ---------------- kernel 3: mean over heads of clipped scores --------------
// grid: B*S, block 256
__global__ void mean_kernel() {
    int bi = blockIdx.x;           // b*512 + i
    int b = bi >> 9, i = bi & 511;
    const float* base = g_scores + ((size_t)b * H * S + i) * S;
    float* dst = g_ma + (size_t)bi * S;
    for (int j = threadIdx.x; j < S; j += blockDim.x) {
        float s = 0.f;
        #pragma unroll
        for (int h = 0; h < H; h++)
            s += nnclip15(base[(size_t)h * S * S + j]);
        dst[j] = s * (1.0f / H);
    }
}

// ---------------- kernel 4: per-row autopoietic transform ------------------
// grid: B*S (one block per (b,i) row), block 256, 2 elems/thread
__global__ void transform_kernel(const float* __restrict__ w1, const float* __restrict__ b1,
                                 const float* __restrict__ w2, const float* __restrict__ b2)
{
    __shared__ float w1s[HID], b1s[HID], w2s[HID];
    __shared__ float red[256];
    int tid = threadIdx.x;
    if (tid < HID) { w1s[tid] = w1[tid]; b1s[tid] = b1[tid]; w2s[tid] = w2[tid]; }
    __syncthreads();

    int bi = blockIdx.x;
    int b = bi >> 9;
    const float* row = g_ma + (size_t)bi * S;
    float ma0 = row[tid], ma1 = row[tid + 256];

    // scalar conv stack: auto(scaled) = clip(sum_h w2[h]*relu(clip(scaled*w1+b1,-5,5)) + b2, -5,5)
    float sc0 = clampf(clampf(ma0, -8.f, 8.f) * 0.05f, -10.f, 10.f);
    float sc1 = clampf(clampf(ma1, -8.f, 8.f) * 0.05f, -10.f, 10.f);
    float au0 = 0.f, au1 = 0.f;
    #pragma unroll 8
    for (int h = 0; h < HID; h++) {
        float w = w1s[h], bb = b1s[h], wv = w2s[h];
        float h0 = fmaxf(clampf(sc0 * w + bb, -5.f, 5.f), 0.f);
        float h1 = fmaxf(clampf(sc1 * w + bb, -5.f, 5.f), 0.f);
        au0 += h0 * wv; au1 += h1 * wv;
    }
    float b2v = b2[0];
    au0 = clampf(au0 + b2v, -5.f, 5.f);
    au1 = clampf(au1 + b2v, -5.f, 5.f);
    float sig0 = 1.f / (1.f + expf(-clampf(1.f + 2.5f * au0, 0.5f, 1.5f)));
    float sig1 = 1.f / (1.f + expf(-clampf(1.f + 2.5f * au1, 0.5f, 1.5f)));

    // entropy-softmax chain
    float cl0 = clampf(ma0, -10.f, 10.f), cl1 = clampf(ma1, -10.f, 10.f);
    float m1 = blockMax(fmaxf(cl0, cl1), red);
    float e0 = expf(cl0 - m1), e1 = expf(cl1 - m1);
    float S1 = blockSum(e0 + e1, red);
    float inv1 = 1.f / S1;
    float p0 = e0 * inv1, p1 = e1 * inv1;
    float H0 = -p0 * logf(p0 + 1e-6f);
    float H1 = -p1 * logf(p1 + 1e-6f);
    float m2 = blockMax(fmaxf(3.f * H0, 3.f * H1), red);
    float f0 = expf(3.f * H0 - m2), f1 = expf(3.f * H1 - m2);
    float S2 = blockSum(f0 + f1, red);
    float inv2 = 1.f / S2;

    float t00 = sig0 * f0 * inv2;
    float t01 = sig1 * f1 * inv2;
    float* tdst = g_t0 + (size_t)bi * S;
    tdst[tid] = t00; tdst[tid + 256] = t01;

    float st    = blockSum(t00 + t01, red);
    float stsq  = blockSum(t00 * t00 + t01 * t01, red);
    float sma   = blockSum(ma0 + ma1, red);
    float smasq = blockSum(ma0 * ma0 + ma1 * ma1, red);
    if (tid == 0) {
        atomicAdd(&g_sums[b * 4 + 0], (double)st);
        atomicAdd(&g_sums[b * 4 + 1], (double)stsq);
        atomicAdd(&g_sums[b * 4 + 2], (double)sma);
        atomicAdd(&g_sums[b * 4 + 3], (double)smasq);
    }
}

// ---------------- kernel 5: per-batch affine scalars -----------------------
// t_final = o_mean + gdyn*gamma*(t0 - m0)  =>  A_b + C_b * t0
__global__ void finalize_kernel() {
    int b = threadIdx.x;
    if (b >= B) return;
    double st    = g_sums[b * 4 + 0];
    double stsq  = g_sums[b * 4 + 1];
    double sma   = g_sums[b * 4 + 2];
    double smasq = g_sums[b * 4 + 3];
    double N = (double)S * (double)S;
    double e_o = sqrt(smasq) + 1e-4;
    double e_t = sqrt(stsq)  + 1e-4;
    double gamma = fmin(fmax(e_o / e_t, 0.8), 1.2);
    double m0 = st / N;
    double var0 = fmax(stsq / N - m0 * m0, 0.0);
    double o_mean = sma / N;
    double varo = fmax(smasq / N - o_mean * o_mean, 0.0);
    double t_std = sqrt(fmax(gamma * gamma * var0, 0.01));
    double o_std = sqrt(fmax(varo, 0.01));
    double gdyn = fmin(fmax(o_std / t_std, 0.8), 1.2);
    double C = gdyn * gamma;
    g_AC[b * 2 + 0] = (float)(o_mean - C * m0);
    g_AC[b * 2 + 1] = (float)C;
}

// ---------------- kernel 6: per-row online softmax stats -------------------
// one warp per row; grid BH*S/8 blocks of 256 (8 warps)
__global__ void rowstat_kernel() {
    int gr = blockIdx.x * 8 + (threadIdx.x >> 5);  // bh*512 + i
    int lane = threadIdx.x & 31;
    int bh = gr >> 9;
    int b  = bh >> 3;
    int i  = gr & 511;
    float Ab = g_AC[b * 2], Cb = g_AC[b * 2 + 1];
    const float* srow = g_scores + (size_t)gr * S;
    const float* trow = g_t0 + ((size_t)(b * S + i)) * S;
    float m = -1e30f, sum = 0.f;
    for (int j = lane; j < S; j += 32) {
        float s = nnclip15(srow[j]);
        s = clampf(s + 0.1f * (Ab + Cb * trow[j]), -15.f, 15.f);
        float mn = fmaxf(m, s);
        sum = sum * expf(m - mn) + expf(s - mn);
        m = mn;
    }
    #pragma unroll
    for (int o = 16; o > 0; o >>= 1) {
        float m2 = __shfl_xor_sync(0xffffffffu, m, o);
        float s2 = __shfl_xor_sync(0xffffffffu, sum, o);
        float mn = fmaxf(m, m2);
        sum = sum * expf(m - mn) + s2 * expf(m2 - mn);
        m = mn;
    }
    if (lane == 0) { g_rowmax[gr] = m; g_rowsum[gr] = sum; }
}

// ---------------- kernel 7: softmax(P) @ V ---------------------------------
// grid: (S/64, BH), block 256
__global__ void attnv_kernel() {
    __shared__ __align__(16) float Ps[64][68];   // [j][r]
    __shared__ __align__(16) float Vs[64][68];   // [j][d]
    __shared__ float rmax[64], rinv[64];
    int bh = blockIdx.y;
    int b = bh >> 3, h = bh & 7;
    int r0 = blockIdx.x * 64;
    int tid = threadIdx.x, tx = tid & 15, ty = tid >> 4;
    float Ab = g_AC[b * 2], Cb = g_AC[b * 2 + 1];
    if (tid < 64) {
        int gr = bh * S + r0 + tid;
        rmax[tid] = g_rowmax[gr];
        rinv[tid] = 1.f / g_rowsum[gr];
    }
    __syncthreads();
    const float* sbase = g_scores + ((size_t)bh * S + r0) * S;
    const float* tbase = g_t0 + ((size_t)(b * S + r0)) * S;
    const float* vbase = g_v + (size_t)bh * S * DH;
    float c[4][4] = {};
    for (int jt = 0; jt < 8; ++jt) {
        #pragma unroll
        for (int l = 0; l < 16; ++l) {
            int idx = tid + l * 256;
            int r = idx >> 6, j = idx & 63;
            float s = nnclip15(sbase[(size_t)r * S + jt * 64 + j]);
            s = clampf(s + 0.1f * (Ab + Cb * tbase[(size_t)r * S + jt * 64 + j]), -15.f, 15.f);
            Ps[j][r] = expf(s - rmax[r]) * rinv[r];
            Vs[r][j] = vbase[(jt * 64 + r) * DH + j];
        }
        __syncthreads();
        #pragma unroll
        for (int kk = 0; kk < 64; ++kk) {
            float4 av = *(const float4*)&Ps[kk][ty * 4];
            float4 bw = *(const float4*)&Vs[kk][tx * 4];
            float a[4] = {av.x, av.y, av.z, av.w};
            float bb[4] = {bw.x, bw.y, bw.z, bw.w};
            #pragma unroll
            for (int i = 0; i < 4; i++)
                #pragma unroll
                for (int j = 0; j < 4; j++)
                    c[i][j] += a[i] * bb[j];
        }
        __syncthreads();
    }
    #pragma unroll
    for (int i = 0; i < 4; i++) {
        int r = r0 + ty * 4 + i;
        float* dst = g_ao + (((size_t)(b * S + r)) * H + h) * DH + tx * 4;
        #pragma unroll
        for (int j = 0; j < 4; j++) dst[j] = c[i][j];
    }
}

// ---------------- kernel 8: output projection -------------------------------
// grid: (E/64, M/64), block 256
__global__ void proj_kernel(const float* __restrict__ wo, const float* __restrict__ bo,
                            float* __restrict__ out)
{
    __shared__ __align__(16) float As[64][68];
    __shared__ __align__(16) float Ws[64][68];
    int n0 = blockIdx.x * 64;
    int m0 = blockIdx.y * 64;
    int tid = threadIdx.x;
    int tx = tid & 15, ty = tid >> 4;
    float c[4][4] = {};
    for (int kt = 0; kt < 8; ++kt) {
        int k0 = kt * 64;
        #pragma unroll
        for (int l = 0; l < 16; ++l) {
            int idx = tid + l * 256;
            int r = idx >> 6, cc = idx & 63;
            As[cc][r] = g_ao[(m0 + r) * E + k0 + cc];
            Ws[cc][r] = wo  [(n0 + r) * E + k0 + cc];
        }
        __syncthreads();
        #pragma unroll
        for (int kk = 0; kk < 64; ++kk) {
            float4 av = *(const float4*)&As[kk][ty * 4];
            float4 bw = *(const float4*)&Ws[kk][tx * 4];
            float a[4] = {av.x, av.y, av.z, av.w};
            float bb[4] = {bw.x, bw.y, bw.z, bw.w};
            #pragma unroll
            for (int i = 0; i < 4; i++)
                #pragma unroll
                for (int j = 0; j < 4; j++)
                    c[i][j] += a[i] * bb[j];
        }
        __syncthreads();
    }
    #pragma unroll
    for (int i = 0; i < 4; i++) {
        int m = m0 + ty * 4 + i;
        #pragma unroll
        for (int j = 0; j < 4; j++) {
            int o = n0 + tx * 4 + j;
            out[(size_t)m * E + o] = c[i][j] + bo[o];
        }
    }
}

// ---------------- launch ----------------------------------------------------
extern "C" void kernel_launch(void* const* d_in, const int* in_sizes, int n_in,
                              void* d_out, int out_size)
{
    const float* x  = (const float*)d_in[0];
    const float* wq = (const float*)d_in[1];
    const float* bq = (const float*)d_in[2];
    const float* wk = (const float*)d_in[3];
    const float* bk = (const float*)d_in[4];
    const float* wv = (const float*)d_in[5];
    const float* bv = (const float*)d_in[6];
    const float* wo = (const float*)d_in[7];
    const float* bo = (const float*)d_in[8];
    const float* w1 = (const float*)d_in[9];
    const float* b1 = (const float*)d_in[10];
    const float* w2 = (const float*)d_in[11];
    const float* b2 = (const float*)d_in[12];
    float* out = (float*)d_out;

    zero_kernel<<<1, 32>>>();
    qkv_kernel<<<dim3(H, M / 64, 3), 256>>>(x, wq, bq, wk, bk, wv, bv);
    scores_kernel<<<dim3(S / 64, S / 64, BH), 256>>>();
    mean_kernel<<<B * S, 256>>>();
    transform_kernel<<<B * S, 256>>>(w1, b1, w2, b2);
    finalize_kernel<<<1, 32>>>();
    rowstat_kernel<<<BH * S / 8, 256>>>();
    attnv_kernel<<<dim3(S / 64, BH), 256>>>();
    proj_kernel<<<dim3(E / 64, M / 64), 256>>>(wo, bo, out);
}

// round 3
// speedup vs baseline: 1.2543x; 1.2543x over previous
#include <cuda_runtime.h>
#include <math.h>

#define B 4
#define S 512
#define E 512
#define H 8
#define DH 64
#define HID 128
#define M (B*S)      // 2048
#define BH (B*H)     // 32

// ---------------- scratch (device globals; no allocation allowed) ----------
__device__ float  g_q[BH*S*DH];              // [b,h,s,d] (q pre-scaled)
__device__ float  g_k[BH*S*DH];
__device__ float  g_v[BH*S*DH];
__device__ float  g_scores[(size_t)BH*S*S];  // raw scores [b,h,i,j]
__device__ float  g_t0[(size_t)B*S*S];       // sig*Fm (pre batch-affine)
__device__ float  g_ao[M*E];                 // attention output [b,s,h,d]
__device__ double g_sums[B*4];               // per-batch: sum t0, t0^2, ma, ma^2
__device__ float  g_AC[B*2];                 // per-batch affine A_b, C_b

// ---------------- helpers --------------------------------------------------
__device__ __forceinline__ float clampf(float x, float lo, float hi) {
    return fminf(fmaxf(x, lo), hi);
}
__device__ __forceinline__ float nnclip15(float x) {
    if (isnan(x)) x = 0.f;
    else if (isinf(x)) x = (x > 0.f) ? 10.f : -10.f;
    return clampf(x, -15.f, 15.f);
}
// adjusted score used by attnv (exp argument with constant shift 15)
__device__ __forceinline__ float adj_e(float raw, float t, float Ab, float Cb) {
    float s = nnclip15(raw);
    s = clampf(s + 0.1f * (Ab + Cb * t), -15.f, 15.f);
    return __expf(s - 15.f);
}

__device__ __forceinline__ float bsum(float v, float* red) {
    #pragma unroll
    for (int o = 16; o; o >>= 1) v += __shfl_xor_sync(0xffffffffu, v, o);
    int w = threadIdx.x >> 5;
    __syncthreads();
    if ((threadIdx.x & 31) == 0) red[w] = v;
    __syncthreads();
    return red[0]+red[1]+red[2]+red[3]+red[4]+red[5]+red[6]+red[7];
}

// ---------------- kernel 0: zero accumulators ------------------------------
__global__ void zero_kernel() {
    int t = threadIdx.x;
    if (t < B*4) g_sums[t] = 0.0;
}

// ---------------- kernel 1: QKV projection (A @ W^T + b) -------------------
// grid: (E/64=8, M/128=16, 3), block 256. Writes [b,h,s,d] layout.
__global__ void __launch_bounds__(256, 2) qkv_kernel(
    const float* __restrict__ x,
    const float* __restrict__ wq, const float* __restrict__ bq,
    const float* __restrict__ wk, const float* __restrict__ bk,
    const float* __restrict__ wv, const float* __restrict__ bv)
{
    __shared__ float As[32][132];
    __shared__ float Bs[32][68];
    int which = blockIdx.z;
    const float* Wp = (which == 0) ? wq : (which == 1) ? wk : wv;
    const float* bp = (which == 0) ? bq : (which == 1) ? bk : bv;
    float* outp     = (which == 0) ? g_q : (which == 1) ? g_k : g_v;
    float scale = (which == 0) ? 0.125f : 1.0f;

    int n0 = blockIdx.x * 64;
    int m0 = blockIdx.y * 128;
    int tid = threadIdx.x, tx = tid & 15, ty = tid >> 4;
    float c[8][4] = {};

    for (int kt = 0; kt < 16; ++kt) {
        int k0 = kt * 32;
        #pragma unroll
        for (int p = 0; p < 4; ++p) {
            int f = tid + p * 256;
            int m = f >> 3, kq = f & 7;
            float4 v = *(const float4*)(x + (size_t)(m0 + m) * E + k0 + kq * 4);
            As[kq*4+0][m] = v.x; As[kq*4+1][m] = v.y;
            As[kq*4+2][m] = v.z; As[kq*4+3][m] = v.w;
        }
        #pragma unroll
        for (int p = 0; p < 2; ++p) {
            int f = tid + p * 256;
            int n = f >> 3, kq = f & 7;
            float4 v = *(const float4*)(Wp + (size_t)(n0 + n) * E + k0 + kq * 4);
            Bs[kq*4+0][n] = v.x; Bs[kq*4+1][n] = v.y;
            Bs[kq*4+2][n] = v.z; Bs[kq*4+3][n] = v.w;
        }
        __syncthreads();
        #pragma unroll
        for (int kk = 0; kk < 32; ++kk) {
            float4 a0 = *(const float4*)&As[kk][ty*8];
            float4 a1 = *(const float4*)&As[kk][ty*8+4];
            float4 bv4 = *(const float4*)&Bs[kk][tx*4];
            float av[8] = {a0.x,a0.y,a0.z,a0.w,a1.x,a1.y,a1.z,a1.w};
            float bb[4] = {bv4.x,bv4.y,bv4.z,bv4.w};
            #pragma unroll
            for (int i = 0; i < 8; ++i)
                #pragma unroll
                for (int j = 0; j < 4; ++j)
                    c[i][j] += av[i] * bb[j];
        }
        __syncthreads();
    }
    int h = n0 >> 6;
    int d0 = tx * 4;
    float4 bias = *(const float4*)(bp + n0 + d0);
    #pragma unroll
    for (int i = 0; i < 8; ++i) {
        int m = m0 + ty * 8 + i;
        int b = m >> 9, s = m & 511;
        float4 o;
        o.x = (c[i][0] + bias.x) * scale;
        o.y = (c[i][1] + bias.y) * scale;
        o.z = (c[i][2] + bias.z) * scale;
        o.w = (c[i][3] + bias.w) * scale;
        *(float4*)(outp + (((size_t)(b * H + h) * S + s) * DH) + d0) = o;
    }
}

// ---------------- kernel 2: scores = q @ k^T per (b,h) ---------------------
// grid: (S/64=8, S/128=4, BH=32), block 256
__global__ void __launch_bounds__(256, 2) scores_kernel() {
    __shared__ float Qs[32][132];
    __shared__ float Ks[32][68];
    int bh = blockIdx.z;
    int i0 = blockIdx.y * 128, j0 = blockIdx.x * 64;
    int tid = threadIdx.x, tx = tid & 15, ty = tid >> 4;
    const float* qb = g_q + (size_t)bh * S * DH;
    const float* kb = g_k + (size_t)bh * S * DH;
    float c[8][4] = {};

    for (int kt = 0; kt < 2; ++kt) {
        int k0 = kt * 32;
        #pragma unroll
        for (int p = 0; p < 4; ++p) {
            int f = tid + p * 256;
            int m = f >> 3, kq = f & 7;
            float4 v = *(const float4*)(qb + (size_t)(i0 + m) * DH + k0 + kq * 4);
            Qs[kq*4+0][m] = v.x; Qs[kq*4+1][m] = v.y;
            Qs[kq*4+2][m] = v.z; Qs[kq*4+3][m] = v.w;
        }
        #pragma unroll
        for (int p = 0; p < 2; ++p) {
            int f = tid + p * 256;
            int n = f >> 3, kq = f & 7;
            float4 v = *(const float4*)(kb + (size_t)(j0 + n) * DH + k0 + kq * 4);
            Ks[kq*4+0][n] = v.x; Ks[kq*4+1][n] = v.y;
            Ks[kq*4+2][n] = v.z; Ks[kq*4+3][n] = v.w;
        }
        __syncthreads();
        #pragma unroll
        for (int kk = 0; kk < 32; ++kk) {
            float4 a0 = *(const float4*)&Qs[kk][ty*8];
            float4 a1 = *(const float4*)&Qs[kk][ty*8+4];
            float4 bv4 = *(const float4*)&Ks[kk][tx*4];
            float av[8] = {a0.x,a0.y,a0.z,a0.w,a1.x,a1.y,a1.z,a1.w};
            float bb[4] = {bv4.x,bv4.y,bv4.z,bv4.w};
            #pragma unroll
            for (int i = 0; i < 8; ++i)
                #pragma unroll
                for (int j = 0; j < 4; ++j)
                    c[i][j] += av[i] * bb[j];
        }
        __syncthreads();
    }
    float* dst = g_scores + ((size_t)bh * S + i0) * S + j0;
    #pragma unroll
    for (int i = 0; i < 8; ++i) {
        float4 o = make_float4(c[i][0], c[i][1], c[i][2], c[i][3]);
        *(float4*)(dst + (size_t)(ty * 8 + i) * S + tx * 4) = o;
    }
}

// ---------------- kernel 3: fused head-mean + autopoietic transform -------
// grid: B*S (one block per (b,i) row), block 256, 2 elems/thread
__global__ void __launch_bounds__(256) transform_kernel(
    const float* __restrict__ w1, const float* __restrict__ b1,
    const float* __restrict__ w2, const float* __restrict__ b2)
{
    __shared__ float w1s[HID], b1s[HID], w2s[HID];
    __shared__ float red[8];
    int tid = threadIdx.x;
    if (tid < HID) { w1s[tid] = w1[tid]; b1s[tid] = b1[tid]; w2s[tid] = w2[tid]; }
    __syncthreads();

    int bi = blockIdx.x;
    int b = bi >> 9, i = bi & 511;
    const float* sbase = g_scores + ((size_t)b * H * S + i) * S;

    // head-mean of clipped scores (fused former mean_kernel)
    float ma0 = 0.f, ma1 = 0.f;
    #pragma unroll
    for (int h = 0; h < H; ++h) {
        ma0 += nnclip15(sbase[(size_t)h * S * S + tid]);
        ma1 += nnclip15(sbase[(size_t)h * S * S + tid + 256]);
    }
    ma0 *= 0.125f; ma1 *= 0.125f;

    // scalar conv stack
    float sc0 = clampf(clampf(ma0, -8.f, 8.f) * 0.05f, -10.f, 10.f);
    float sc1 = clampf(clampf(ma1, -8.f, 8.f) * 0.05f, -10.f, 10.f);
    float au0 = 0.f, au1 = 0.f;
    #pragma unroll 8
    for (int h = 0; h < HID; h++) {
        float w = w1s[h], bb = b1s[h], wv = w2s[h];
        float h0 = fmaxf(clampf(sc0 * w + bb, -5.f, 5.f), 0.f);
        float h1 = fmaxf(clampf(sc1 * w + bb, -5.f, 5.f), 0.f);
        au0 += h0 * wv; au1 += h1 * wv;
    }
    float b2v = b2[0];
    au0 = clampf(au0 + b2v, -5.f, 5.f);
    au1 = clampf(au1 + b2v, -5.f, 5.f);
    float sig0 = 1.f / (1.f + __expf(-clampf(1.f + 2.5f * au0, 0.5f, 1.5f)));
    float sig1 = 1.f / (1.f + __expf(-clampf(1.f + 2.5f * au1, 0.5f, 1.5f)));

    // entropy chain; cl <= 10 so constant shift 10 (exp <= 1, no max pass)
    float cl0 = clampf(ma0, -10.f, 10.f), cl1 = clampf(ma1, -10.f, 10.f);
    float e0 = __expf(cl0 - 10.f), e1 = __expf(cl1 - 10.f);
    float S1 = bsum(e0 + e1, red);
    float inv1 = 1.f / S1;
    float p0 = e0 * inv1, p1 = e1 * inv1;
    float H0 = -p0 * __logf(p0 + 1e-6f);
    float H1 = -p1 * __logf(p1 + 1e-6f);
    // 3H in [0, ~1.2] -> exp safe without shift
    float f0 = __expf(3.f * H0), f1 = __expf(3.f * H1);
    float S2 = bsum(f0 + f1, red);
    float inv2 = 1.f / S2;

    float t00 = sig0 * f0 * inv2;
    float t01 = sig1 * f1 * inv2;
    float* tdst = g_t0 + (size_t)bi * S;
    tdst[tid] = t00; tdst[tid + 256] = t01;

    float st    = bsum(t00 + t01, red);
    float stsq  = bsum(t00 * t00 + t01 * t01, red);
    float sma   = bsum(ma0 + ma1, red);
    float smasq = bsum(ma0 * ma0 + ma1 * ma1, red);
    if (tid == 0) {
        atomicAdd(&g_sums[b * 4 + 0], (double)st);
        atomicAdd(&g_sums[b * 4 + 1], (double)stsq);
        atomicAdd(&g_sums[b * 4 + 2], (double)sma);
        atomicAdd(&g_sums[b * 4 + 3], (double)smasq);
    }
}

// ---------------- kernel 4: per-batch affine scalars -----------------------
__global__ void finalize_kernel() {
    int b = threadIdx.x;
    if (b >= B) return;
    double st    = g_sums[b * 4 + 0];
    double stsq  = g_sums[b * 4 + 1];
    double sma   = g_sums[b * 4 + 2];
    double smasq = g_sums[b * 4 + 3];
    double N = (double)S * (double)S;
    double e_o = sqrt(smasq) + 1e-4;
    double e_t = sqrt(stsq)  + 1e-4;
    double gamma = fmin(fmax(e_o / e_t, 0.8), 1.2);
    double m0 = st / N;
    double var0 = fmax(stsq / N - m0 * m0, 0.0);
    double o_mean = sma / N;
    double varo = fmax(smasq / N - o_mean * o_mean, 0.0);
    double t_std = sqrt(fmax(gamma * gamma * var0, 0.01));
    double o_std = sqrt(fmax(varo, 0.01));
    double gdyn = fmin(fmax(o_std / t_std, 0.8), 1.2);
    double C = gdyn * gamma;
    g_AC[b * 2 + 0] = (float)(o_mean - C * m0);
    g_AC[b * 2 + 1] = (float)C;
}

// ---------------- kernel 5: flash-style softmax(P) @ V with fused rowsum ---
// grid: (S/128=4, BH=32), block 256
__global__ void __launch_bounds__(256, 2) attnv_kernel() {
    __shared__ float Ps[32][132];   // [j][i], unnormalized exp
    __shared__ float Vs[32][68];    // [j][d]
    __shared__ float rinv_s[128];
    int bh = blockIdx.y;
    int b = bh >> 3, h = bh & 7;
    int r0 = blockIdx.x * 128;
    int tid = threadIdx.x, tx = tid & 15, ty = tid >> 4;
    float Ab = g_AC[b * 2], Cb = g_AC[b * 2 + 1];

    const float* sbase = g_scores + ((size_t)bh * S + r0) * S;
    const float* tbase = g_t0 + ((size_t)(b * S + r0)) * S;
    const float* vbase = g_v + (size_t)bh * S * DH;

    float c[8][4] = {};
    float rs[4] = {};   // row partial sums for rows (tid>>3) + 32p

    for (int kt = 0; kt < 16; ++kt) {
        int j0c = kt * 32;
        // P tile: compute exp(adj - 15) on the fly
        #pragma unroll
        for (int p = 0; p < 4; ++p) {
            int f = tid + p * 256;
            int jq = f & 7, ii = f >> 3;
            const float* sp = sbase + (size_t)ii * S + j0c + jq * 4;
            const float* tp = tbase + (size_t)ii * S + j0c + jq * 4;
            float4 sv = *(const float4*)sp;
            float4 tv = *(const float4*)tp;
            float e0 = adj_e(sv.x, tv.x, Ab, Cb);
            float e1 = adj_e(sv.y, tv.y, Ab, Cb);
            float e2 = adj_e(sv.z, tv.z, Ab, Cb);
            float e3 = adj_e(sv.w, tv.w, Ab, Cb);
            Ps[jq*4+0][ii] = e0; Ps[jq*4+1][ii] = e1;
            Ps[jq*4+2][ii] = e2; Ps[jq*4+3][ii] = e3;
            rs[p] += e0 + e1 + e2 + e3;
        }
        // V tile [32][64]
        #pragma unroll
        for (int p = 0; p < 2; ++p) {
            int f = tid + p * 256;
            int j = f >> 4, dq = f & 15;
            float4 v = *(const float4*)(vbase + (size_t)(j0c + j) * DH + dq * 4);
            *(float4*)&Vs[j][dq * 4] = v;
        }
        __syncthreads();
        #pragma unroll
        for (int kk = 0; kk < 32; ++kk) {
            float4 a0 = *(const float4*)&Ps[kk][ty*8];
            float4 a1 = *(const float4*)&Ps[kk][ty*8+4];
            float4 bv4 = *(const float4*)&Vs[kk][tx*4];
            float av[8] = {a0.x,a0.y,a0.z,a0.w,a1.x,a1.y,a1.z,a1.w};
            float bb[4] = {bv4.x,bv4.y,bv4.z,bv4.w};
            #pragma unroll
            for (int i = 0; i < 8; ++i)
                #pragma unroll
                for (int j = 0; j < 4; ++j)
                    c[i][j] += av[i] * bb[j];
        }
        __syncthreads();
    }

    // reduce row sums across the 8 lanes sharing each row
    #pragma unroll
    for (int p = 0; p < 4; ++p) {
        #pragma unroll
        for (int o = 1; o < 8; o <<= 1)
            rs[p] += __shfl_xor_sync(0xffffffffu, rs[p], o);
    }
    if ((tid & 7) == 0) {
        int a = tid >> 3;
        #pragma unroll
        for (int p = 0; p < 4; ++p)
            rinv_s[a + 32 * p] = 1.f / rs[p];
    }
    __syncthreads();

    #pragma unroll
    for (int i = 0; i < 8; ++i) {
        int r = r0 + ty * 8 + i;
        float ri = rinv_s[ty * 8 + i];
        float4 o = make_float4(c[i][0]*ri, c[i][1]*ri, c[i][2]*ri, c[i][3]*ri);
        *(float4*)(g_ao + (((size_t)(b * S + r)) * H + h) * DH + tx * 4) = o;
    }
}

// ---------------- kernel 6: output projection -------------------------------
// grid: (E/64=8, M/128=16), block 256
__global__ void __launch_bounds__(256, 2) proj_kernel(
    const float* __restrict__ wo, const float* __restrict__ bo,
    float* __restrict__ out)
{
    __shared__ float As[32][132];
    __shared__ float Bs[32][68];
    int n0 = blockIdx.x * 64;
    int m0 = blockIdx.y * 128;
    int tid = threadIdx.x, tx = tid & 15, ty = tid >> 4;
    float c[8][4] = {};

    for (int kt = 0; kt < 16; ++kt) {
        int k0 = kt * 32;
        #pragma unroll
        for (int p = 0; p < 4; ++p) {
            int f = tid + p * 256;
            int m = f >> 3, kq = f & 7;
            float4 v = *(const float4*)(g_ao + (size_t)(m0 + m) * E + k0 + kq * 4);
            As[kq*4+0][m] = v.x; As[kq*4+1][m] = v.y;
            As[kq*4+2][m] = v.z; As[kq*4+3][m] = v.w;
        }
        #pragma unroll
        for (int p = 0; p < 2; ++p) {
            int f = tid + p * 256;
            int n = f >> 3, kq = f & 7;
            float4 v = *(const float4*)(wo + (size_t)(n0 + n) * E + k0 + kq * 4);
            Bs[kq*4+0][n] = v.x; Bs[kq*4+1][n] = v.y;
            Bs[kq*4+2][n] = v.z; Bs[kq*4+3][n] = v.w;
        }
        __syncthreads();
        #pragma unroll
        for (int kk = 0; kk < 32; ++kk) {
            float4 a0 = *(const float4*)&As[kk][ty*8];
            float4 a1 = *(const float4*)&As[kk][ty*8+4];
            float4 bv4 = *(const float4*)&Bs[kk][tx*4];
            float av[8] = {a0.x,a0.y,a0.z,a0.w,a1.x,a1.y,a1.z,a1.w};
            float bb[4] = {bv4.x,bv4.y,bv4.z,bv4.w};
            #pragma unroll
            for (int i = 0; i < 8; ++i)
                #pragma unroll
                for (int j = 0; j < 4; ++j)
                    c[i][j] += av[i] * bb[j];
        }
        __syncthreads();
    }
    float4 bias = *(const float4*)(bo + n0 + tx * 4);
    #pragma unroll
    for (int i = 0; i < 8; ++i) {
        int m = m0 + ty * 8 + i;
        float4 o = make_float4(c[i][0]+bias.x, c[i][1]+bias.y,
                               c[i][2]+bias.z, c[i][3]+bias.w);
        *(float4*)(out + (size_t)m * E + n0 + tx * 4) = o;
    }
}

// ---------------- launch ----------------------------------------------------
extern "C" void kernel_launch(void* const* d_in, const int* in_sizes, int n_in,
                              void* d_out, int out_size)
{
    const float* x  = (const float*)d_in[0];
    const float* wq = (const float*)d_in[1];
    const float* bq = (const float*)d_in[2];
    const float* wk = (const float*)d_in[3];
    const float* bk = (const float*)d_in[4];
    const float* wv = (const float*)d_in[5];
    const float* bv = (const float*)d_in[6];
    const float* wo = (const float*)d_in[7];
    const float* bo = (const float*)d_in[8];
    const float* w1 = (const float*)d_in[9];
    const float* b1 = (const float*)d_in[10];
    const float* w2 = (const float*)d_in[11];
    const float* b2 = (const float*)d_in[12];
    float* out = (float*)d_out;

    zero_kernel<<<1, 32>>>();
    qkv_kernel<<<dim3(E / 64, M / 128, 3), 256>>>(x, wq, bq, wk, bk, wv, bv);
    scores_kernel<<<dim3(S / 64, S / 128, BH), 256>>>();
    transform_kernel<<<B * S, 256>>>(w1, b1, w2, b2);
    finalize_kernel<<<1, 32>>>();
    attnv_kernel<<<dim3(S / 128, BH), 256>>>();
    proj_kernel<<<dim3(E / 64, M / 128), 256>>>(wo, bo, out);
}